// round 14
// baseline (speedup 1.0000x reference)
#include <cuda_runtime.h>
#include <cstdint>

#define NBLK 148
#define TPB  512
#define GSZ  20971520   // 128*512*320
#define NC   163840     // 512*320

// dynamic smem: 2 A-stages (32KB each) | mbars | resident B (swizzled, unpadded)
#define STG_B     32768
#define MBAR_OFF  65536
#define BRES_OFF  65664
#define BSLOT_B   81920          // light B slot: 64 cols x 320 floats x 4
#define SMEM_DYN  229504         // 65664 + 163840

// ---------------- static device scratch ----------------
__device__ __align__(16) float d_T0[29 * 1280];      // layer0 preact per label (incl bias), cell-major
__device__ __align__(16) float d_B1[1280];           // layer1 bias, cell-major
__device__ __align__(16) float d_W0m[1280 * 320];    // layer0 w_hh, [p][k], perm64 rows, tf32
__device__ __align__(16) float d_W1m[1280 * 640];    // layer1 [w_ih|w_hh], [p][k], perm64, tf32
__device__ __align__(16) float d_A0c[2][5 * 512 * 64];  // layer0 h, 64-chunk-major swizzled
__device__ __align__(16) float d_A1c[2][10 * 512 * 64]; // layer1 in: ch 0..4 ys0, 5..9 h1
__device__ __align__(16) float d_C0[512 * 320];      // layer0 c, [n][c]
__device__ __align__(16) float d_C1[512 * 320];      // layer1 c
__device__ unsigned g_genA[4 * 32];
__device__ unsigned g_cntA[4 * 32];

// ---------------- helpers ----------------
__device__ __forceinline__ float sigf(float v)   { return __fdividef(1.0f, 1.0f + __expf(-v)); }
__device__ __forceinline__ float tanhf_(float v) { return __fdividef(2.0f, 1.0f + __expf(-2.0f * v)) - 1.0f; }
__device__ __forceinline__ unsigned ld_acq(const unsigned* p) {
    unsigned v; asm volatile("ld.acquire.gpu.u32 %0, [%1];" : "=r"(v) : "l"(p) : "memory"); return v;
}
__device__ __forceinline__ void st_rel(unsigned* p, unsigned v) {
    asm volatile("st.release.gpu.u32 [%0], %1;" :: "l"(p), "r"(v) : "memory");
}
__device__ __forceinline__ float tf32_rne(float f) {
    uint32_t u = __float_as_uint(f);
    u = (u + 0xFFFu + ((u >> 13) & 1u)) & 0xFFFFE000u;
    return __uint_as_float(u);
}
__device__ __forceinline__ void ldm4(uint32_t& r0, uint32_t& r1, uint32_t& r2, uint32_t& r3, uint32_t addr) {
    asm volatile("ldmatrix.sync.aligned.m8n8.x4.shared.b16 {%0,%1,%2,%3}, [%4];"
                 : "=r"(r0), "=r"(r1), "=r"(r2), "=r"(r3) : "r"(addr));
}
__device__ __forceinline__ void mma8(float* d, const uint32_t* a, uint32_t b0, uint32_t b1) {
    asm volatile(
        "mma.sync.aligned.m16n8k8.row.col.f32.tf32.tf32.f32 "
        "{%0,%1,%2,%3}, {%4,%5,%6,%7}, {%8,%9}, {%0,%1,%2,%3};"
        : "+f"(d[0]), "+f"(d[1]), "+f"(d[2]), "+f"(d[3])
        : "r"(a[0]), "r"(a[1]), "r"(a[2]), "r"(a[3]), "r"(b0), "r"(b1));
}
__device__ __forceinline__ void bulk_ld(uint32_t dst, const void* src, uint32_t mbar) {
    asm volatile("mbarrier.arrive.expect_tx.shared.b64 _, [%0], %1;" :: "r"(mbar), "r"(32768u) : "memory");
    asm volatile("cp.async.bulk.shared::cluster.global.mbarrier::complete_tx::bytes [%0], [%1], %2, [%3];"
                 :: "r"(dst), "l"(src), "r"(32768u), "r"(mbar) : "memory");
}
__device__ __forceinline__ void waitp(uint32_t mb, int ph) {
    asm volatile(
        "{\n\t.reg .pred P;\n"
        "W%=:\n\t"
        "mbarrier.try_wait.parity.acquire.cta.shared::cta.b64 P, [%0], %1, 0x989680;\n\t"
        "@P bra.uni D%=;\n\t"
        "bra.uni W%=;\n"
        "D%=:\n\t}"
        :: "r"(mb), "r"((unsigned)ph) : "memory");
}

// perm64: output col p (tile width 64) -> natural gate row j = gate*320 + cell.
__host__ __device__ __forceinline__ int perm_j64(int p) {
    const int t = p & 63;
    const int wc = t >> 5, r = t & 31;
    const int ni = r >> 3, rm = r & 7;
    const int cell = (p >> 6) * 16 + wc * 8 + (rm >> 1) + ((ni >> 1) << 2);
    const int gate = ((ni & 1) << 1) | (rm & 1);
    return gate * 320 + cell;
}
// 64-wide chunk-major swizzled A float index within a chunk for (n, c64)
__host__ __device__ __forceinline__ int aswz64(int n, int c64) {
    const int seg = c64 >> 2;
    return n * 64 + (((seg ^ (n & 7)) << 2) | (c64 & 3));
}

// ---------------- prep kernels ----------------
__global__ void prep_wt(const float* __restrict__ w_ih, const float* __restrict__ w_hh) {
    const int st = gridDim.x * blockDim.x;
    const int i0 = blockIdx.x * blockDim.x + threadIdx.x;
    for (int i = i0; i < 1280 * 320; i += st) {
        const int p = i / 320, k = i - p * 320;
        d_W0m[i] = tf32_rne(w_hh[perm_j64(p) * 320 + k]);
    }
    for (int i = i0; i < 1280 * 640; i += st) {
        const int p = i / 640, k = i - p * 640;
        const int j = perm_j64(p);
        d_W1m[i] = tf32_rne((k < 320) ? w_ih[409600 + j * 320 + k]
                                      : w_hh[409600 + j * 320 + (k - 320)]);
    }
}

__global__ void prep_t0(const float* __restrict__ emb, const float* __restrict__ w_ih,
                        const float* __restrict__ b_ih, const float* __restrict__ b_hh) {
    const int v = blockIdx.x / 10;
    const int p = (blockIdx.x % 10) * 128 + threadIdx.x;
    const int j = (p & 3) * 320 + (p >> 2);          // cell-major: p = cell*4+gate
    float acc = b_ih[j] + b_hh[j];
    if (v < 28) {
        const float* er = emb + v * 320;
        const float* wr = w_ih + j * 320;
#pragma unroll 4
        for (int k = 0; k < 320; k += 4) {
            const float4 e = *reinterpret_cast<const float4*>(er + k);
            const float4 w = *reinterpret_cast<const float4*>(wr + k);
            acc += e.x * w.x + e.y * w.y + e.z * w.z + e.w * w.w;
        }
    }
    d_T0[v * 1280 + p] = acc;
}

__global__ void prep_state(const float* __restrict__ h0, const float* __restrict__ c0,
                           const float* __restrict__ b_ih, const float* __restrict__ b_hh) {
    const int st = gridDim.x * blockDim.x;
    const int i0 = blockIdx.x * blockDim.x + threadIdx.x;
    for (int i = i0; i < NC; i += st) {
        const int n = i / 320, c = i - n * 320;
        d_A0c[0][(c >> 6) * 32768 + aswz64(n, c & 63)] = tf32_rne(h0[i]);
        d_A1c[1][(5 + (c >> 6)) * 32768 + aswz64(n, c & 63)] = tf32_rne(h0[NC + i]);
        d_C0[i] = c0[i];
        d_C1[i] = c0[NC + i];
    }
    for (int i = i0; i < 1280; i += st) {
        const int j = (i & 3) * 320 + (i >> 2);
        d_B1[i] = b_ih[1280 + j] + b_hh[1280 + j];
    }
    if (i0 < 4) { g_genA[i0 * 32] = 0u; g_cntA[i0 * 32] = 0u; }
}

// ---------------- persistent LSTM kernel ----------------
// 4 row groups x 128 rows; 37 CTAs/group: r<20 heavy (layer1, K=640, p0=r*64);
// r>=20 light (layer0, K=320): r2=r-20 owns tile r2 and (r2<3) also 17+r2.
// Tile 128 rows x 64 perm cols; 16 warps = 2 K-sets x (4 wrow x 2 wcol);
// warp tile 32x32; in-chunk split-K (set0 ks 0-3, set1 ks 4-7); smem reduction.
__global__ void __launch_bounds__(TPB, 1)
lstm_pers(const int* __restrict__ x, float* __restrict__ out) {
    extern __shared__ __align__(16) char dsm[];
    const uint32_t sbase = (uint32_t)__cvta_generic_to_shared(dsm);
    const uint32_t mb0 = sbase + MBAR_OFF;
    const uint32_t BresB = sbase + BRES_OFF;
    float* red = (float*)dsm;                       // reduction buffer aliases stage0

    const int tx = threadIdx.x;
    const int lane = tx & 31, wid = tx >> 5;
    const int ksp = wid >> 3, w8 = wid & 7;
    const int wr = w8 >> 1, wc = w8 & 1;
    const int g_ = lane >> 2, q_ = lane & 3;
    const int sub = lane >> 3, subrow = lane & 7;
    const int b = blockIdx.x;
    const int grp = b / 37, r = b - grp * 37;
    const int heavy = (r < 20);
    const int n0 = grp * 128;
    const int Kdim = heavy ? 640 : 320;
    const int K4 = Kdim * 4;
    const int nch = Kdim >> 6;                     // 10 heavy, 5 light
    const int ntile = heavy ? 1 : ((r - 20) < 3 ? 2 : 1);
    int p0s[2];
    if (heavy) { p0s[0] = r * 64; p0s[1] = 0; }
    else       { p0s[0] = (r - 20) * 64; p0s[1] = (17 + (r - 20)) * 64; }

    // ---- one-time: init mbars, load resident B (swizzled) ----
    if (tx == 0) {
#pragma unroll
        for (int i = 0; i < 2; ++i)
            asm volatile("mbarrier.init.shared.b64 [%0], %1;" :: "r"(mb0 + i * 8), "r"(1u) : "memory");
    }
    for (int ti = 0; ti < ntile; ++ti) {
        const float* Wg = heavy ? (d_W1m + p0s[ti] * 640) : (d_W0m + p0s[ti] * 320);
        const int nseg = Kdim >> 2;
        for (int i = tx; i < 64 * nseg; i += TPB) {
            const int col = i / nseg, seg = i - col * nseg;
            const int dstb = ti * BSLOT_B + col * K4 + ((seg * 16) ^ ((col & 7) << 4));
            *reinterpret_cast<float4*>(dsm + BRES_OFF + dstb) =
                *reinterpret_cast<const float4*>(Wg + col * Kdim + seg * 4);
        }
    }
    __syncthreads();

    // ldsm lane constants
    const uint32_t xr = (uint32_t)(subrow << 4);
    uint32_t rbaseA[2];
#pragma unroll
    for (int mi = 0; mi < 2; ++mi)
        rbaseA[mi] = (uint32_t)((wr * 32 + mi * 16 + (sub & 1) * 8 + subrow) * 256);
    const uint32_t s16A = (uint32_t)((sub >> 1) * 16);
    uint32_t colbaseB[2];
#pragma unroll
    for (int nb = 0; nb < 2; ++nb)
        colbaseB[nb] = (uint32_t)((wc * 32 + nb * 16 + (sub >> 1) * 8 + subrow) * K4);
    const uint32_t s16B = (uint32_t)((sub & 1) * 16);
    const uint32_t ksb = (uint32_t)(ksp * 128);    // split-K byte offset (4 ks * 32B)

    int ph[2] = {0, 0};

    for (int s = 0; s < 129; ++s) {
        const int par = s & 1;
        const int active = heavy ? (s >= 1) : (s < 128);
        if (active) {
            const float* Asrc = heavy ? d_A1c[par] : d_A0c[par];
            const int u = heavy ? (s - 1) : s;
            float* Cst = heavy ? d_C1 : d_C0;

            for (int ti = 0; ti < ntile; ++ti) {
                const int p0 = p0s[ti];
                const uint32_t Bti = BresB + (uint32_t)(ti * BSLOT_B);

                // prefetch c-state + labels (set0 only uses these)
                float cpre[2][2][2];
                int labv[2][2];
#pragma unroll
                for (int mi = 0; mi < 2; ++mi)
#pragma unroll
                    for (int rs = 0; rs < 2; ++rs) {
                        const int n = n0 + wr * 32 + mi * 16 + g_ + rs * 8;
                        if (!heavy && ksp == 0) labv[mi][rs] = x[u * 512 + n];
#pragma unroll
                        for (int cs = 0; cs < 2; ++cs) {
                            const int cellg = (p0 >> 2) + wc * 8 + q_ + cs * 4;
                            if (ksp == 0) cpre[mi][rs][cs] = Cst[n * 320 + cellg];
                        }
                    }

                float acc[2][4][4];
#pragma unroll
                for (int mi = 0; mi < 2; ++mi)
#pragma unroll
                    for (int ni = 0; ni < 4; ++ni)
#pragma unroll
                        for (int e = 0; e < 4; ++e) acc[mi][ni][e] = 0.0f;

                __syncthreads();                    // stage/red region free before reload
                if (tx == 0) {
                    bulk_ld(sbase,         Asrc + 0 * 32768 + n0 * 64, mb0);
                    bulk_ld(sbase + STG_B, Asrc + 1 * 32768 + n0 * 64, mb0 + 8);
                }

                for (int ch = 0; ch < nch; ++ch) {
                    const int sl = ch & 1;
                    waitp(mb0 + sl * 8, ph[sl]); ph[sl] ^= 1;
                    const uint32_t stA = sbase + (uint32_t)sl * STG_B;
                    const uint32_t chB = Bti + (uint32_t)ch * 256 + ksb;
#pragma unroll
                    for (int ks = 0; ks < 4; ++ks) {
                        const uint32_t kA = ksb + (uint32_t)(ks * 32);
                        const uint32_t swzA = (kA + s16A) ^ xr;
                        const uint32_t swzB = ((uint32_t)(ks * 32) + s16B) ^ xr;
                        uint32_t a[2][4], bb[2][4];
                        ldm4(a[0][0], a[0][1], a[0][2], a[0][3], stA + rbaseA[0] + swzA);
                        ldm4(a[1][0], a[1][1], a[1][2], a[1][3], stA + rbaseA[1] + swzA);
                        ldm4(bb[0][0], bb[0][1], bb[0][2], bb[0][3], chB + colbaseB[0] + swzB);
                        ldm4(bb[1][0], bb[1][1], bb[1][2], bb[1][3], chB + colbaseB[1] + swzB);
#pragma unroll
                        for (int mi = 0; mi < 2; ++mi) {
                            mma8(acc[mi][0], a[mi], bb[0][0], bb[0][1]);
                            mma8(acc[mi][1], a[mi], bb[0][2], bb[0][3]);
                            mma8(acc[mi][2], a[mi], bb[1][0], bb[1][1]);
                            mma8(acc[mi][3], a[mi], bb[1][2], bb[1][3]);
                        }
                    }
                    __syncthreads();                 // all warps done with stage sl
                    if (tx == 0 && ch + 2 < nch)     // refill consumed stage
                        bulk_ld(sbase + (uint32_t)sl * STG_B,
                                Asrc + (size_t)(ch + 2) * 32768 + n0 * 64, mb0 + sl * 8);
                }

                // ---- split-K reduction: set1 -> smem, set0 adds ----
                if (ksp == 1) {
                    float* dst = red + w8 * 1024;
#pragma unroll
                    for (int mi = 0; mi < 2; ++mi)
#pragma unroll
                        for (int ni = 0; ni < 4; ++ni)
#pragma unroll
                            for (int e = 0; e < 4; ++e)
                                dst[((mi * 4 + ni) * 4 + e) * 32 + lane] = acc[mi][ni][e];
                }
                __syncthreads();
                if (ksp == 0) {
                    const float* src = red + w8 * 1024;
#pragma unroll
                    for (int mi = 0; mi < 2; ++mi)
#pragma unroll
                        for (int ni = 0; ni < 4; ++ni)
#pragma unroll
                            for (int e = 0; e < 4; ++e)
                                acc[mi][ni][e] += src[((mi * 4 + ni) * 4 + e) * 32 + lane];

                    // ---- epilogue (set0): 8 LSTM cells per thread ----
#pragma unroll
                    for (int mi = 0; mi < 2; ++mi) {
#pragma unroll
                        for (int rs = 0; rs < 2; ++rs) {
                            const int n = n0 + wr * 32 + mi * 16 + g_ + rs * 8;
                            const float* tb = heavy ? d_B1 : (d_T0 + labv[mi][rs] * 1280);
#pragma unroll
                            for (int cs = 0; cs < 2; ++cs) {
                                const int cellg = (p0 >> 2) + wc * 8 + q_ + cs * 4;
                                const float4 t = *reinterpret_cast<const float4*>(tb + cellg * 4);
                                const float pi = acc[mi][cs * 2 + 0][rs * 2 + 0] + t.x;
                                const float pf = acc[mi][cs * 2 + 0][rs * 2 + 1] + t.y;
                                const float pg = acc[mi][cs * 2 + 1][rs * 2 + 0] + t.z;
                                const float po = acc[mi][cs * 2 + 1][rs * 2 + 1] + t.w;
                                const float ii = sigf(pi), ff = sigf(pf);
                                const float gg = tanhf_(pg), oo = sigf(po);
                                const int ci = n * 320 + cellg;
                                const float c = ff * cpre[mi][rs][cs] + ii * gg;
                                Cst[ci] = c;
                                const float h = oo * tanhf_(c);
                                const float hr = tf32_rne(h);
                                const int wsw = aswz64(n, cellg & 63);
                                if (heavy) {
                                    out[(size_t)u * NC + ci] = h;
                                    d_A1c[par ^ 1][(5 + (cellg >> 6)) * 32768 + wsw] = hr;
                                    if (u == 127) { out[GSZ + NC + ci] = h; out[GSZ + 3 * NC + ci] = c; }
                                } else {
                                    d_A0c[par ^ 1][(cellg >> 6) * 32768 + wsw] = hr;
                                    d_A1c[par ^ 1][(cellg >> 6) * 32768 + wsw] = hr;
                                    if (u == 127) { out[GSZ + ci] = h; out[GSZ + 2 * NC + ci] = c; }
                                }
                            }
                        }
                    }
                }
            }
        }

        // ---- group barrier (37 CTAs, release/acquire) ----
        __syncthreads();
        if (tx == 0) {
            __threadfence();
            const unsigned arrived = atomicAdd(&g_cntA[grp * 32], 1u);
            if (arrived == 36u) {
                g_cntA[grp * 32] = 0u;
                __threadfence();
                st_rel(&g_genA[grp * 32], (unsigned)(s + 1));
            } else {
                while (ld_acq(&g_genA[grp * 32]) <= (unsigned)s) __nanosleep(32);
            }
        }
        __syncthreads();
    }
}

// ---------------- launcher ----------------
extern "C" void kernel_launch(void* const* d_in, const int* in_sizes, int n_in,
                              void* d_out, int out_size) {
    const int*   x    = (const int*)d_in[0];
    const float* h0   = (const float*)d_in[1];
    const float* c0   = (const float*)d_in[2];
    const float* emb  = (const float*)d_in[3];
    const float* w_ih = (const float*)d_in[4];
    const float* w_hh = (const float*)d_in[5];
    const float* b_ih = (const float*)d_in[6];
    const float* b_hh = (const float*)d_in[7];

    cudaFuncSetAttribute(lstm_pers, cudaFuncAttributeMaxDynamicSharedMemorySize, SMEM_DYN);

    prep_wt<<<512, 256>>>(w_ih, w_hh);
    prep_t0<<<290, 128>>>(emb, w_ih, b_ih, b_hh);
    prep_state<<<256, 256>>>(h0, c0, b_ih, b_hh);
    lstm_pers<<<NBLK, TPB, SMEM_DYN>>>(x, (float*)d_out);
}

// round 15
// speedup vs baseline: 1.0849x; 1.0849x over previous
#include <cuda_runtime.h>
#include <cstdint>

#define NBLK 148
#define TPB  512
#define GSZ  20971520   // 128*512*320
#define NC   163840     // 512*320

// dynamic smem: 2 A-stages (32KB each) | mbars(full0,full1,empty0,empty1) | resident B
#define STG_B     32768
#define MBAR_OFF  65536
#define BRES_OFF  65664
#define BSLOT_B   81920          // light B slot: 64 cols x 320 floats x 4
#define SMEM_DYN  229504         // 65664 + 163840

// ---------------- static device scratch ----------------
__device__ __align__(16) float d_T0[29 * 1280];      // layer0 preact per label (incl bias), cell-major
__device__ __align__(16) float d_B1[1280];           // layer1 bias, cell-major
__device__ __align__(16) float d_W0m[1280 * 320];    // layer0 w_hh, [p][k], perm16 rows, tf32
__device__ __align__(16) float d_W1m[1280 * 640];    // layer1 [w_ih|w_hh], [p][k], perm16, tf32
__device__ __align__(16) float d_A0c[2][5 * 512 * 64];  // layer0 h, 64-chunk-major swizzled
__device__ __align__(16) float d_A1c[2][10 * 512 * 64]; // layer1 in: ch 0..4 ys0, 5..9 h1
__device__ __align__(16) float d_C0[512 * 320];      // layer0 c, [n][c]
__device__ __align__(16) float d_C1[512 * 320];      // layer1 c
__device__ unsigned g_genA[4 * 32];
__device__ unsigned g_cntA[4 * 32];

// ---------------- helpers ----------------
__device__ __forceinline__ float sigf(float v)   { return __fdividef(1.0f, 1.0f + __expf(-v)); }
__device__ __forceinline__ float tanhf_(float v) { return __fdividef(2.0f, 1.0f + __expf(-2.0f * v)) - 1.0f; }
__device__ __forceinline__ unsigned ld_acq(const unsigned* p) {
    unsigned v; asm volatile("ld.acquire.gpu.u32 %0, [%1];" : "=r"(v) : "l"(p) : "memory"); return v;
}
__device__ __forceinline__ void st_rel(unsigned* p, unsigned v) {
    asm volatile("st.release.gpu.u32 [%0], %1;" :: "l"(p), "r"(v) : "memory");
}
__device__ __forceinline__ float tf32_rne(float f) {
    uint32_t u = __float_as_uint(f);
    u = (u + 0xFFFu + ((u >> 13) & 1u)) & 0xFFFFE000u;
    return __uint_as_float(u);
}
__device__ __forceinline__ void ldm4(uint32_t& r0, uint32_t& r1, uint32_t& r2, uint32_t& r3, uint32_t addr) {
    asm volatile("ldmatrix.sync.aligned.m8n8.x4.shared.b16 {%0,%1,%2,%3}, [%4];"
                 : "=r"(r0), "=r"(r1), "=r"(r2), "=r"(r3) : "r"(addr));
}
__device__ __forceinline__ void mma8(float* d, const uint32_t* a, uint32_t b0, uint32_t b1) {
    asm volatile(
        "mma.sync.aligned.m16n8k8.row.col.f32.tf32.tf32.f32 "
        "{%0,%1,%2,%3}, {%4,%5,%6,%7}, {%8,%9}, {%0,%1,%2,%3};"
        : "+f"(d[0]), "+f"(d[1]), "+f"(d[2]), "+f"(d[3])
        : "r"(a[0]), "r"(a[1]), "r"(a[2]), "r"(a[3]), "r"(b0), "r"(b1));
}
__device__ __forceinline__ void bulk_ld(uint32_t dst, const void* src, uint32_t mbar) {
    asm volatile("mbarrier.arrive.expect_tx.shared.b64 _, [%0], %1;" :: "r"(mbar), "r"(32768u) : "memory");
    asm volatile("cp.async.bulk.shared::cluster.global.mbarrier::complete_tx::bytes [%0], [%1], %2, [%3];"
                 :: "r"(dst), "l"(src), "r"(32768u), "r"(mbar) : "memory");
}
__device__ __forceinline__ void waitp(uint32_t mb, int ph) {
    asm volatile(
        "{\n\t.reg .pred P;\n"
        "W%=:\n\t"
        "mbarrier.try_wait.parity.acquire.cta.shared::cta.b64 P, [%0], %1, 0x989680;\n\t"
        "@P bra.uni D%=;\n\t"
        "bra.uni W%=;\n"
        "D%=:\n\t}"
        :: "r"(mb), "r"((unsigned)ph) : "memory");
}
__device__ __forceinline__ void mbar_arrive(uint32_t mb) {
    asm volatile("mbarrier.arrive.release.cta.shared::cta.b64 _, [%0];" :: "r"(mb) : "memory");
}

// perm16: output col p -> natural gate row j = gate*320 + cell.
__host__ __device__ __forceinline__ int perm_j16(int p) {
    const int tcol = p & 63;
    const int wcol = tcol >> 4, t = tcol & 15;
    const int ni = t >> 3, rm = t & 7;
    const int cell = (p >> 6) * 16 + wcol * 4 + (rm >> 1);
    const int gate = ((ni & 1) << 1) | (rm & 1);
    return gate * 320 + cell;
}
// 64-wide chunk-major swizzled A float index within a chunk for (n, c64)
__host__ __device__ __forceinline__ int aswz64(int n, int c64) {
    const int seg = c64 >> 2;
    return n * 64 + (((seg ^ (n & 7)) << 2) | (c64 & 3));
}

// ---------------- prep kernels ----------------
__global__ void prep_wt(const float* __restrict__ w_ih, const float* __restrict__ w_hh) {
    const int st = gridDim.x * blockDim.x;
    const int i0 = blockIdx.x * blockDim.x + threadIdx.x;
    for (int i = i0; i < 1280 * 320; i += st) {
        const int p = i / 320, k = i - p * 320;
        d_W0m[i] = tf32_rne(w_hh[perm_j16(p) * 320 + k]);
    }
    for (int i = i0; i < 1280 * 640; i += st) {
        const int p = i / 640, k = i - p * 640;
        const int j = perm_j16(p);
        d_W1m[i] = tf32_rne((k < 320) ? w_ih[409600 + j * 320 + k]
                                      : w_hh[409600 + j * 320 + (k - 320)]);
    }
}

__global__ void prep_t0(const float* __restrict__ emb, const float* __restrict__ w_ih,
                        const float* __restrict__ b_ih, const float* __restrict__ b_hh) {
    const int v = blockIdx.x / 10;
    const int p = (blockIdx.x % 10) * 128 + threadIdx.x;
    const int j = (p & 3) * 320 + (p >> 2);          // cell-major: p = cell*4+gate
    float acc = b_ih[j] + b_hh[j];
    if (v < 28) {
        const float* er = emb + v * 320;
        const float* wr = w_ih + j * 320;
#pragma unroll 4
        for (int k = 0; k < 320; k += 4) {
            const float4 e = *reinterpret_cast<const float4*>(er + k);
            const float4 w = *reinterpret_cast<const float4*>(wr + k);
            acc += e.x * w.x + e.y * w.y + e.z * w.z + e.w * w.w;
        }
    }
    d_T0[v * 1280 + p] = acc;
}

__global__ void prep_state(const float* __restrict__ h0, const float* __restrict__ c0,
                           const float* __restrict__ b_ih, const float* __restrict__ b_hh) {
    const int st = gridDim.x * blockDim.x;
    const int i0 = blockIdx.x * blockDim.x + threadIdx.x;
    for (int i = i0; i < NC; i += st) {
        const int n = i / 320, c = i - n * 320;
        d_A0c[0][(c >> 6) * 32768 + aswz64(n, c & 63)] = tf32_rne(h0[i]);
        d_A1c[1][(5 + (c >> 6)) * 32768 + aswz64(n, c & 63)] = tf32_rne(h0[NC + i]);
        d_C0[i] = c0[i];
        d_C1[i] = c0[NC + i];
    }
    for (int i = i0; i < 1280; i += st) {
        const int j = (i & 3) * 320 + (i >> 2);
        d_B1[i] = b_ih[1280 + j] + b_hh[1280 + j];
    }
    if (i0 < 4) { g_genA[i0 * 32] = 0u; g_cntA[i0 * 32] = 0u; }
}

// ---------------- persistent LSTM kernel ----------------
// 4 row groups x 128 rows; 37 CTAs/group: r<20 heavy (layer1, K=640, p0=r*64);
// r>=20 light (layer0, K=320): r2=r-20 owns tile r2 and (r2<3) also 17+r2.
// Tile 128 rows x 64 perm cols; 16 warps 4x4; warp tile 32x16; thread 4 cells.
// B resident, XOR-swizzled. A via cp.async.bulk, 2-stage ring with full/empty
// mbarriers (NO per-chunk __syncthreads): consumers stream, producer=tx0.
__global__ void __launch_bounds__(TPB, 1)
lstm_pers(const int* __restrict__ x, float* __restrict__ out) {
    extern __shared__ __align__(16) char dsm[];
    const uint32_t sbase = (uint32_t)__cvta_generic_to_shared(dsm);
    const uint32_t mbF0 = sbase + MBAR_OFF;        // full stage0
    const uint32_t mbF1 = sbase + MBAR_OFF + 8;    // full stage1
    const uint32_t mbE0 = sbase + MBAR_OFF + 16;   // empty stage0 (count 16)
    const uint32_t mbE1 = sbase + MBAR_OFF + 24;   // empty stage1
    const uint32_t BresB = sbase + BRES_OFF;

    const int tx = threadIdx.x;
    const int lane = tx & 31, wid = tx >> 5;
    const int wrow = wid >> 2, wcol = wid & 3;
    const int g_ = lane >> 2, q_ = lane & 3;
    const int sub = lane >> 3, subrow = lane & 7;
    const int b = blockIdx.x;
    const int grp = b / 37, r = b - grp * 37;
    const int heavy = (r < 20);
    const int n0 = grp * 128;
    const int Kdim = heavy ? 640 : 320;
    const int K4 = Kdim * 4;
    const int nch = Kdim >> 6;                     // 10 heavy, 5 light
    const int ntile = heavy ? 1 : ((r - 20) < 3 ? 2 : 1);
    int p0s[2];
    if (heavy) { p0s[0] = r * 64; p0s[1] = 0; }
    else       { p0s[0] = (r - 20) * 64; p0s[1] = (17 + (r - 20)) * 64; }

    // ---- one-time: init mbars, load resident B (swizzled) ----
    if (tx == 0) {
        asm volatile("mbarrier.init.shared.b64 [%0], %1;" :: "r"(mbF0), "r"(1u) : "memory");
        asm volatile("mbarrier.init.shared.b64 [%0], %1;" :: "r"(mbF1), "r"(1u) : "memory");
        asm volatile("mbarrier.init.shared.b64 [%0], %1;" :: "r"(mbE0), "r"(16u) : "memory");
        asm volatile("mbarrier.init.shared.b64 [%0], %1;" :: "r"(mbE1), "r"(16u) : "memory");
    }
    for (int ti = 0; ti < ntile; ++ti) {
        const float* Wg = heavy ? (d_W1m + p0s[ti] * 640) : (d_W0m + p0s[ti] * 320);
        const int nseg = Kdim >> 2;
        for (int i = tx; i < 64 * nseg; i += TPB) {
            const int col = i / nseg, seg = i - col * nseg;
            const int dstb = ti * BSLOT_B + col * K4 + ((seg * 16) ^ ((col & 7) << 4));
            *reinterpret_cast<float4*>(dsm + BRES_OFF + dstb) =
                *reinterpret_cast<const float4*>(Wg + col * Kdim + seg * 4);
        }
    }
    __syncthreads();
    // prime both empty barriers (one round each): first producer waits pass
    if (lane == 0) { mbar_arrive(mbE0); mbar_arrive(mbE1); }

    // ldsm lane constants
    const uint32_t xr = (uint32_t)(subrow << 4);
    uint32_t rbaseA[2];
#pragma unroll
    for (int mi = 0; mi < 2; ++mi)
        rbaseA[mi] = (uint32_t)((wrow * 32 + mi * 16 + (sub & 1) * 8 + subrow) * 256);
    const uint32_t s16A = (uint32_t)((sub >> 1) * 16);
    const uint32_t colbaseB = (uint32_t)((wcol * 16 + (sub >> 1) * 8 + subrow) * K4);
    const uint32_t s16B = (uint32_t)((sub & 1) * 16);

    int phF[2] = {0, 0};                           // full phases (all threads)
    int phE[2] = {0, 0};                           // empty phases (tx0 only meaningful)
    const uint32_t mbF[2] = {mbF0, mbF1};
    const uint32_t mbE[2] = {mbE0, mbE1};

    for (int s = 0; s < 129; ++s) {
        const int par = s & 1;
        const int active = heavy ? (s >= 1) : (s < 128);
        if (active) {
            const float* Asrc = heavy ? d_A1c[par] : d_A0c[par];
            const int u = heavy ? (s - 1) : s;
            float* Cst = heavy ? d_C1 : d_C0;

            for (int ti = 0; ti < ntile; ++ti) {
                const int p0 = p0s[ti];
                const uint32_t Bti = BresB + (uint32_t)(ti * BSLOT_B) + colbaseB;

                // prefetch c-state + labels
                float cpre[2][2];
                int labv[2][2];
                const int cellg = (p0 >> 2) + wcol * 4 + q_;
#pragma unroll
                for (int mi = 0; mi < 2; ++mi)
#pragma unroll
                    for (int rs = 0; rs < 2; ++rs) {
                        const int n = n0 + wrow * 32 + mi * 16 + g_ + rs * 8;
                        if (!heavy) labv[mi][rs] = x[u * 512 + n];
                        cpre[mi][rs] = Cst[n * 320 + cellg];
                    }

                float acc[2][2][4];
#pragma unroll
                for (int mi = 0; mi < 2; ++mi)
#pragma unroll
                    for (int ni = 0; ni < 2; ++ni)
#pragma unroll
                        for (int e = 0; e < 4; ++e) acc[mi][ni][e] = 0.0f;

                // producer preload: stages 0,1 (wait empty -> bulk load)
                if (tx == 0) {
#pragma unroll
                    for (int c = 0; c < 2; ++c) {
                        if (c < nch) {
                            waitp(mbE[c], phE[c]); phE[c] ^= 1;
                            bulk_ld(sbase + (uint32_t)c * STG_B,
                                    Asrc + (size_t)c * 32768 + n0 * 64, mbF[c]);
                        }
                    }
                }

                for (int ch = 0; ch < nch; ++ch) {
                    const int sl = ch & 1;
                    waitp(mbF[sl], phF[sl]); phF[sl] ^= 1;
                    const uint32_t stA = sbase + (uint32_t)sl * STG_B;
                    const uint32_t chB = Bti + (uint32_t)ch * 256;
#pragma unroll
                    for (int ks = 0; ks < 8; ++ks) {
                        const uint32_t swzA = ((uint32_t)(ks * 32) + s16A) ^ xr;
                        const uint32_t swzB = ((uint32_t)(ks * 32) + s16B) ^ xr;
                        uint32_t a[2][4], bb[4];
                        ldm4(a[0][0], a[0][1], a[0][2], a[0][3], stA + rbaseA[0] + swzA);
                        ldm4(a[1][0], a[1][1], a[1][2], a[1][3], stA + rbaseA[1] + swzA);
                        ldm4(bb[0], bb[1], bb[2], bb[3], chB + swzB);
#pragma unroll
                        for (int mi = 0; mi < 2; ++mi) {
                            mma8(acc[mi][0], a[mi], bb[0], bb[1]);
                            mma8(acc[mi][1], a[mi], bb[2], bb[3]);
                        }
                    }
                    if (lane == 0) mbar_arrive(mbE[sl]);      // warp done reading stage sl
                    if (tx == 0 && ch + 2 < nch) {            // refill stage sl for ch+2
                        waitp(mbE[sl], phE[sl]); phE[sl] ^= 1;
                        bulk_ld(sbase + (uint32_t)sl * STG_B,
                                Asrc + (size_t)(ch + 2) * 32768 + n0 * 64, mbF[sl]);
                    }
                }

                // ---- epilogue: 2 mi x 2 rows, 1 cell, all 4 gates in-regs ----
#pragma unroll
                for (int mi = 0; mi < 2; ++mi) {
#pragma unroll
                    for (int rs = 0; rs < 2; ++rs) {
                        const int n = n0 + wrow * 32 + mi * 16 + g_ + rs * 8;
                        const float* tb = heavy ? d_B1 : (d_T0 + labv[mi][rs] * 1280);
                        const float4 t = *reinterpret_cast<const float4*>(tb + cellg * 4);
                        const float pi = acc[mi][0][rs * 2 + 0] + t.x;
                        const float pf = acc[mi][0][rs * 2 + 1] + t.y;
                        const float pg = acc[mi][1][rs * 2 + 0] + t.z;
                        const float po = acc[mi][1][rs * 2 + 1] + t.w;
                        const float ii = sigf(pi), ff = sigf(pf);
                        const float gg = tanhf_(pg), oo = sigf(po);
                        const int ci = n * 320 + cellg;
                        const float c = ff * cpre[mi][rs] + ii * gg;
                        Cst[ci] = c;
                        const float h = oo * tanhf_(c);
                        const float hr = tf32_rne(h);
                        const int wsw = aswz64(n, cellg & 63);
                        if (heavy) {
                            out[(size_t)u * NC + ci] = h;
                            d_A1c[par ^ 1][(5 + (cellg >> 6)) * 32768 + wsw] = hr;
                            if (u == 127) { out[GSZ + NC + ci] = h; out[GSZ + 3 * NC + ci] = c; }
                        } else {
                            d_A0c[par ^ 1][(cellg >> 6) * 32768 + wsw] = hr;
                            d_A1c[par ^ 1][(cellg >> 6) * 32768 + wsw] = hr;
                            if (u == 127) { out[GSZ + ci] = h; out[GSZ + 2 * NC + ci] = c; }
                        }
                    }
                }
            }
        }

        // ---- group barrier (37 CTAs, release/acquire) ----
        __syncthreads();
        if (tx == 0) {
            __threadfence();
            const unsigned arrived = atomicAdd(&g_cntA[grp * 32], 1u);
            if (arrived == 36u) {
                g_cntA[grp * 32] = 0u;
                __threadfence();
                st_rel(&g_genA[grp * 32], (unsigned)(s + 1));
            } else {
                while (ld_acq(&g_genA[grp * 32]) <= (unsigned)s) __nanosleep(32);
            }
        }
        __syncthreads();
    }
}

// ---------------- launcher ----------------
extern "C" void kernel_launch(void* const* d_in, const int* in_sizes, int n_in,
                              void* d_out, int out_size) {
    const int*   x    = (const int*)d_in[0];
    const float* h0   = (const float*)d_in[1];
    const float* c0   = (const float*)d_in[2];
    const float* emb  = (const float*)d_in[3];
    const float* w_ih = (const float*)d_in[4];
    const float* w_hh = (const float*)d_in[5];
    const float* b_ih = (const float*)d_in[6];
    const float* b_hh = (const float*)d_in[7];

    cudaFuncSetAttribute(lstm_pers, cudaFuncAttributeMaxDynamicSharedMemorySize, SMEM_DYN);

    prep_wt<<<512, 256>>>(w_ih, w_hh);
    prep_t0<<<290, 128>>>(emb, w_ih, b_ih, b_hh);
    prep_state<<<256, 256>>>(h0, c0, b_ih, b_hh);
    lstm_pers<<<NBLK, TPB, SMEM_DYN>>>(x, (float*)d_out);
}